// round 11
// baseline (speedup 1.0000x reference)
#include <cuda_runtime.h>
#include <cuda_bf16.h>
#include <stdint.h>

#define NPG  39
#define FDIM 3280
#define BGR  4096
#define MAXE (NPG * 9)

#define OFF_RES1 39
#define OFF_RES2 351
#define OFF_RES3 2847
#define OFF_OUT0 3198
#define OFF_OUT1 3199
#define OFF_OUT2 3207
#define OFF_OUT3 3271

// GEMM1 (int8): K=3280 -> K1Q=3328 (mult of 128), slices double bytes
// GEMM2 (bf16 3-term): K=5000 -> K2P=5056, K2T=15168
#define K1Q 3328
#define K2P 5056
#define K2T (3*K2P)
#define N1PAD 5120

__device__ float g_F[(size_t)BGR * FDIM];
__device__ float g_G[(size_t)BGR * 5000];
__device__ float g_H[(size_t)BGR * 1024];
__device__ __align__(128) int8_t g_A1q[(size_t)BGR * 2 * K1Q];
__device__ __align__(128) int8_t g_B1q[(size_t)N1PAD * 2 * K1Q];
__device__ float g_sa1[BGR];
__device__ float g_sb1[N1PAD];
__device__ __nv_bfloat16 g_A2[(size_t)BGR * K2T];
__device__ __nv_bfloat16 g_B2[(size_t)1024 * K2T];
__device__ int g_is64;

__device__ __forceinline__ uint32_t smem_u32(const void* p) {
    uint32_t a;
    asm("{ .reg .u64 t; cvta.to.shared.u64 t, %1; cvt.u32.u64 %0, t; }"
        : "=r"(a) : "l"(p));
    return a;
}

// ===================== misc small kernels =====================
__global__ void k_sniff(const int* __restrict__ ei) {
    if (threadIdx.x == 0) g_is64 = (ei[8] == 0) ? 1 : 0;
}

__global__ void k_res0(const float* __restrict__ x, float* __restrict__ F) {
    int g = blockIdx.x;
    __shared__ float sx[NPG];
    int t = threadIdx.x;
    if (t < NPG) {
        float v = x[g * NPG + t];
        sx[t] = v;
        F[(size_t)g * FDIM + t] = v;
    }
    __syncthreads();
    if (t == 0) {
        float mv = sx[0];
        for (int i = 1; i < NPG; i++) mv = fmaxf(mv, sx[i]);
        F[(size_t)g * FDIM + OFF_OUT0] = mv;
    }
}

__device__ __forceinline__ unsigned fenc(float f) {
    unsigned u = __float_as_uint(f);
    return (u & 0x80000000u) ? ~u : (u | 0x80000000u);
}
__device__ __forceinline__ float fdec(unsigned u) {
    return (u & 0x80000000u) ? __uint_as_float(u & 0x7FFFFFFFu)
                             : __uint_as_float(~u);
}

// ===================== GAT layer (counting-sort + float4, R8) =====================
template <int FIN, int FOUT>
__global__ __launch_bounds__(256) void k_gat(
    const float* __restrict__ X, int gstride,
    const void* __restrict__ edges, int E, int EPG,
    const float* __restrict__ W, const float* __restrict__ as_,
    const float* __restrict__ ad_, const float* __restrict__ bias,
    float* __restrict__ F, int res_off, int max_off)
{
    __shared__ __align__(16) float sx[NPG * FIN];
    __shared__ __align__(16) float sW[FIN * FOUT];
    __shared__ float sas[FOUT], sad[FOUT], sb[FOUT];
    __shared__ __align__(16) float sh[NPG * FOUT];
    __shared__ __align__(16) float sout[NPG * FOUT];
    __shared__ float ss[NPG], sd[NPG], sden[NPG];
    __shared__ unsigned sm[NPG];
    __shared__ float ew[MAXE];
    __shared__ short els[MAXE], eld[MAXE];
    __shared__ short sse[MAXE];
    __shared__ float sew[MAXE];
    __shared__ int cnt[NPG + 1], off[NPG];

    constexpr bool V4 = (FOUT % 4 == 0);

    int g = blockIdx.x;
    int t = threadIdx.x;
    const float* xg = X + (size_t)g * gstride;
    int nE = EPG + NPG;

    for (int i = t; i < NPG * FIN; i += 256) sx[i] = xg[i];
    for (int i = t; i < FIN * FOUT; i += 256) sW[i] = W[i];
    if (t < FOUT) { sas[t] = as_[t]; sad[t] = ad_[t]; sb[t] = bias[t]; }
    if (t < NPG + 1) cnt[t] = 0;
    __syncthreads();

    if (V4) {
        constexpr int F4 = FOUT / 4;
        for (int idx = t; idx < NPG * F4; idx += 256) {
            int i = idx / F4, f4 = idx - i * F4;
            float4 a = make_float4(0.f, 0.f, 0.f, 0.f);
            #pragma unroll
            for (int k = 0; k < FIN; k++) {
                float xv = sx[i * FIN + k];
                float4 wv = *(const float4*)&sW[k * FOUT + f4 * 4];
                a.x += xv * wv.x; a.y += xv * wv.y;
                a.z += xv * wv.z; a.w += xv * wv.w;
            }
            *(float4*)&sh[i * FOUT + f4 * 4] = a;
        }
    } else {
        for (int idx = t; idx < NPG * FOUT; idx += 256) {
            int i = idx / FOUT, f = idx - i * FOUT;
            float a = 0.f;
            #pragma unroll
            for (int k = 0; k < FIN; k++) a += sx[i * FIN + k] * sW[k * FOUT + f];
            sh[idx] = a;
        }
    }
    __syncthreads();

    for (int i = t; i < NPG; i += 256) {
        float a = 0.f, b = 0.f;
        #pragma unroll
        for (int f = 0; f < FOUT; f++) {
            a += sh[i * FOUT + f] * sas[f];
            b += sh[i * FOUT + f] * sad[f];
        }
        ss[i] = a; sd[i] = b; sm[i] = 0u;
    }
    __syncthreads();

    bool is64 = (g_is64 != 0);
    long long node0 = (long long)g * NPG;

    for (int e = t; e < nE; e += 256) {
        int ls, ld;
        if (e < EPG) {
            long long ge = (long long)g * EPG + e;
            long long sv, dv;
            if (is64) {
                const long long* p = (const long long*)edges;
                sv = p[ge]; dv = p[ge + E];
            } else {
                const int* p = (const int*)edges;
                sv = p[ge]; dv = p[ge + E];
            }
            ls = (int)(sv - node0);
            ld = (int)(dv - node0);
        } else {
            ls = ld = e - EPG;
        }
        els[e] = (short)ls; eld[e] = (short)ld;
        float ev = ss[ls] + sd[ld];
        ev = ev > 0.f ? ev : 0.2f * ev;
        ew[e] = ev;
        atomicMax(&sm[ld], fenc(ev));
        atomicAdd(&cnt[ld], 1);
    }
    __syncthreads();

    if (t == 0) {
        int s = 0;
        for (int i = 0; i < NPG; i++) {
            int c = cnt[i];
            cnt[i] = s; off[i] = s;
            s += c;
        }
        cnt[NPG] = s;
    }
    __syncthreads();

    for (int e = t; e < nE; e += 256) {
        int ld = eld[e];
        int pos = atomicAdd(&off[ld], 1);
        sew[pos] = __expf(ew[e] - fdec(sm[ld]));
        sse[pos] = els[e];
    }
    __syncthreads();

    for (int i = t; i < NPG; i += 256) {
        float s = 0.f;
        for (int e = cnt[i]; e < cnt[i + 1]; e++) s += sew[e];
        sden[i] = s;
    }
    __syncthreads();

    float* Fg = F + (size_t)g * FDIM;
    if (V4) {
        constexpr int F4 = FOUT / 4;
        for (int idx = t; idx < NPG * F4; idx += 256) {
            int i = idx / F4, f4 = idx - i * F4;
            float4 a = make_float4(0.f, 0.f, 0.f, 0.f);
            int e0 = cnt[i], e1 = cnt[i + 1];
            for (int e = e0; e < e1; e++) {
                float w = sew[e];
                float4 hv = *(const float4*)&sh[(int)sse[e] * FOUT + f4 * 4];
                a.x += w * hv.x; a.y += w * hv.y;
                a.z += w * hv.z; a.w += w * hv.w;
            }
            float inv = 1.f / (sden[i] + 1e-16f);
            int base = i * FOUT + f4 * 4;
            float v0 = fmaxf(a.x * inv + sb[f4 * 4 + 0], 0.f);
            float v1 = fmaxf(a.y * inv + sb[f4 * 4 + 1], 0.f);
            float v2 = fmaxf(a.z * inv + sb[f4 * 4 + 2], 0.f);
            float v3 = fmaxf(a.w * inv + sb[f4 * 4 + 3], 0.f);
            *(float4*)&sout[base] = make_float4(v0, v1, v2, v3);
            Fg[res_off + base + 0] = v0;
            Fg[res_off + base + 1] = v1;
            Fg[res_off + base + 2] = v2;
            Fg[res_off + base + 3] = v3;
        }
    } else {
        for (int idx = t; idx < NPG * FOUT; idx += 256) {
            int i = idx / FOUT, f = idx - i * FOUT;
            float a = 0.f;
            int e0 = cnt[i], e1 = cnt[i + 1];
            for (int e = e0; e < e1; e++)
                a += sew[e] * sh[(int)sse[e] * FOUT + f];
            float v = a / (sden[i] + 1e-16f) + sb[f];
            v = fmaxf(v, 0.f);
            Fg[res_off + idx] = v;
            sout[idx] = v;
        }
    }
    __syncthreads();
    for (int f = t; f < FOUT; f += 256) {
        float mv = sout[f];
        for (int i = 1; i < NPG; i++) mv = fmaxf(mv, sout[i * FOUT + f]);
        Fg[max_off + f] = mv;
    }
}

// ===================== int8 quantization (2 slices, per-row scale) ========
// layout per row: chunk c (128 k's): [q0 x128 | q1 x128] at byte c*256
__global__ __launch_bounds__(256) void k_quantA(
    const float* __restrict__ src, int8_t* __restrict__ dst,
    float* __restrict__ sa, int K, int Kq)
{
    int m = blockIdx.x, t = threadIdx.x;
    const float* row = src + (size_t)m * K;
    __shared__ float red[256];
    float mx = 0.f;
    for (int k = t; k < K; k += 256) mx = fmaxf(mx, fabsf(row[k]));
    red[t] = mx;
    __syncthreads();
    for (int o = 128; o; o >>= 1) {
        if (t < o) red[t] = fmaxf(red[t], red[t + o]);
        __syncthreads();
    }
    float maxv = red[0];
    float s = (maxv > 0.f) ? maxv / 127.f : 1.f;
    float inv = 1.f / s;
    if (t == 0) sa[m] = s;
    int8_t* d = dst + (size_t)m * 2 * Kq;
    for (int k = t; k < K; k += 256) {
        float x = row[k] * inv;
        int q0 = __float2int_rn(x);
        q0 = max(-127, min(127, q0));
        float r = x - (float)q0;
        int q1 = __float2int_rn(r * 256.f);
        q1 = max(-128, min(127, q1));
        int off = ((k >> 7) << 8) + (k & 127);
        d[off] = (int8_t)q0;
        d[off + 128] = (int8_t)q1;
    }
}

// W [K, N] column n -> int8 slices row n (transpose via smem buffer)
__global__ __launch_bounds__(256) void k_quantB(
    const float* __restrict__ W, int8_t* __restrict__ dst,
    float* __restrict__ sbv, int K, int N, int Kq)
{
    int n = blockIdx.x, t = threadIdx.x;
    __shared__ float buf[K1Q];
    __shared__ float red[256];
    for (int k = t; k < K; k += 256) buf[k] = W[(size_t)k * N + n];
    __syncthreads();
    float mx = 0.f;
    for (int k = t; k < K; k += 256) mx = fmaxf(mx, fabsf(buf[k]));
    red[t] = mx;
    __syncthreads();
    for (int o = 128; o; o >>= 1) {
        if (t < o) red[t] = fmaxf(red[t], red[t + o]);
        __syncthreads();
    }
    float maxv = red[0];
    float s = (maxv > 0.f) ? maxv / 127.f : 1.f;
    float inv = 1.f / s;
    if (t == 0) sbv[n] = s;
    int8_t* d = dst + (size_t)n * 2 * Kq;
    for (int k = t; k < K; k += 256) {
        float x = buf[k] * inv;
        int q0 = __float2int_rn(x);
        q0 = max(-127, min(127, q0));
        float r = x - (float)q0;
        int q1 = __float2int_rn(r * 256.f);
        q1 = max(-128, min(127, q1));
        int off = ((k >> 7) << 8) + (k & 127);
        d[off] = (int8_t)q0;
        d[off + 128] = (int8_t)q1;
    }
}

// ===================== bf16 split kernels (GEMM2 path) =====================
__global__ __launch_bounds__(256) void k_splitA(
    const float* __restrict__ src, __nv_bfloat16* __restrict__ dst,
    int K, int Kp)
{
    int m = blockIdx.x;
    const float4* srow = (const float4*)(src + (size_t)m * K);
    __nv_bfloat16* drow = dst + (size_t)m * (3 * Kp);
    int K4 = K >> 2;
    for (int k4 = threadIdx.x; k4 < K4; k4 += 256) {
        float4 v = srow[k4];
        __nv_bfloat162 h01 = __floats2bfloat162_rn(v.x, v.y);
        __nv_bfloat162 h23 = __floats2bfloat162_rn(v.z, v.w);
        __nv_bfloat162 l01 = __floats2bfloat162_rn(
            v.x - __bfloat162float(h01.x), v.y - __bfloat162float(h01.y));
        __nv_bfloat162 l23 = __floats2bfloat162_rn(
            v.z - __bfloat162float(h23.x), v.w - __bfloat162float(h23.y));
        uint2 hp = make_uint2(*(uint32_t*)&h01, *(uint32_t*)&h23);
        uint2 lp = make_uint2(*(uint32_t*)&l01, *(uint32_t*)&l23);
        *(uint2*)(drow + k4 * 4) = hp;
        *(uint2*)(drow + Kp + k4 * 4) = hp;
        *(uint2*)(drow + 2 * Kp + k4 * 4) = lp;
    }
}

__global__ void k_splitB(const float* __restrict__ W, __nv_bfloat16* __restrict__ Bt,
                         int K, int N, int Kp)
{
    __shared__ float tile[32][33];
    int kb = blockIdx.y * 32, nb = blockIdx.x * 32;
    int tx = threadIdx.x, ty = threadIdx.y;
    for (int r = ty; r < 32; r += 8) {
        int k = kb + r, n = nb + tx;
        tile[r][tx] = (k < K && n < N) ? W[(size_t)k * N + n] : 0.f;
    }
    __syncthreads();
    for (int r = ty; r < 32; r += 8) {
        int n = nb + r, k = kb + tx;
        if (n < N && k < K) {
            float v = tile[tx][r];
            __nv_bfloat16 hi = __float2bfloat16(v);
            __nv_bfloat16 lo = __float2bfloat16(v - __bfloat162float(hi));
            __nv_bfloat16* row = Bt + (size_t)n * (3 * Kp);
            row[k] = hi;
            row[Kp + k] = lo;
            row[2 * Kp + k] = hi;
        }
    }
}

// ===================== shared mma helpers =====================
__device__ __forceinline__ void ldm4(uint32_t* r, uint32_t addr) {
    asm volatile("ldmatrix.sync.aligned.m8n8.x4.shared.b16 {%0,%1,%2,%3}, [%4];"
        : "=r"(r[0]), "=r"(r[1]), "=r"(r[2]), "=r"(r[3]) : "r"(addr));
}
__device__ __forceinline__ void mma16816(float* c, const uint32_t* a,
                                         uint32_t b0, uint32_t b1) {
    asm volatile("mma.sync.aligned.m16n8k16.row.col.f32.bf16.bf16.f32 "
        "{%0,%1,%2,%3}, {%4,%5,%6,%7}, {%8,%9}, {%0,%1,%2,%3};"
        : "+f"(c[0]), "+f"(c[1]), "+f"(c[2]), "+f"(c[3])
        : "r"(a[0]), "r"(a[1]), "r"(a[2]), "r"(a[3]), "r"(b0), "r"(b1));
}
__device__ __forceinline__ void mmas8(int* c, const uint32_t* a,
                                      uint32_t b0, uint32_t b1) {
    asm volatile("mma.sync.aligned.m16n8k32.row.col.s32.s8.s8.s32 "
        "{%0,%1,%2,%3}, {%4,%5,%6,%7}, {%8,%9}, {%0,%1,%2,%3};"
        : "+r"(c[0]), "+r"(c[1]), "+r"(c[2]), "+r"(c[3])
        : "r"(a[0]), "r"(a[1]), "r"(a[2]), "r"(a[3]), "r"(b0), "r"(b1));
}

// ===================== int8 GEMM1 =====================
// CTA 128x128, 256 thr, 8 warps (2x4), warp tile 64x32, 3 products.
// stage row = 256 B ([A0 128 | A1 128]) + 16 pad = 272 B.
#define QROWB 272
#define QA_STG (128 * QROWB)
#define QSTG (2 * QA_STG)
#define QSMEM (3 * QSTG)   // 208896

__global__ __launch_bounds__(256, 1) void k_mmai8(
    const int8_t* __restrict__ A, const int8_t* __restrict__ B,
    const float* __restrict__ sav, const float* __restrict__ sbv,
    const float* __restrict__ bias, float* __restrict__ C,
    int Kq, int steps, int Nreal)
{
    extern __shared__ char smem[];
    uint32_t sbse = smem_u32(smem);
    int tid = threadIdx.x;
    int lane = tid & 31, wid = tid >> 5;
    int wm = wid & 1, wn = wid >> 1;          // 2 x 4 warps
    int bm = blockIdx.y * 128, bn = blockIdx.x * 128;
    size_t gs = (size_t)2 * Kq;

    const char* Ab = (const char*)A + (size_t)bm * gs;
    const char* Bb = (const char*)B + (size_t)bn * gs;

    auto load_stage = [&](int s, int slot) {
        size_t kb = (size_t)s * 256;
        uint32_t base = sbse + slot * QSTG;
        #pragma unroll
        for (int i = 0; i < 8; i++) {
            int c = tid + i * 256;
            int row = c >> 4, kc = c & 15;
            uint32_t dst = base + row * QROWB + kc * 16;
            const char* src = Ab + (size_t)row * gs + kb + kc * 16;
            asm volatile("cp.async.cg.shared.global [%0], [%1], 16;"
                         :: "r"(dst), "l"(src));
        }
        #pragma unroll
        for (int i = 0; i < 8; i++) {
            int c = tid + i * 256;
            int row = c >> 4, kc = c & 15;
            uint32_t dst = base + QA_STG + row * QROWB + kc * 16;
            const char* src = Bb + (size_t)row * gs + kb + kc * 16;
            asm volatile("cp.async.cg.shared.global [%0], [%1], 16;"
                         :: "r"(dst), "l"(src));
        }
    };

    int accP[4][4][4], accX[4][4][4];
    #pragma unroll
    for (int i = 0; i < 4; i++)
        #pragma unroll
        for (int j = 0; j < 4; j++)
            #pragma unroll
            for (int q = 0; q < 4; q++) { accP[i][j][q] = 0; accX[i][j][q] = 0; }

    load_stage(0, 0);
    asm volatile("cp.async.commit_group;" ::: "memory");
    load_stage(1, 1);
    asm volatile("cp.async.commit_group;" ::: "memory");

    int lr = lane & 15;
    int lc = (lane >> 4) * 16;

    for (int j = 0; j < steps; j++) {
        asm volatile("cp.async.wait_group 1;" ::: "memory");
        __syncthreads();

        if (j + 2 < steps) load_stage(j + 2, (j + 2) % 3);
        asm volatile("cp.async.commit_group;" ::: "memory");

        uint32_t sA = sbse + (j % 3) * QSTG;
        uint32_t sB = sA + QA_STG;
        uint32_t aA = sA + (wm * 64 + lr) * QROWB + lc;
        uint32_t aB = sB + (wn * 32 + lr) * QROWB + lc;

        #pragma unroll
        for (int ks = 0; ks < 4; ks++) {
            uint32_t a0[4][4], a1[4][4], b0[2][4], b1[2][4];
            #pragma unroll
            for (int mi = 0; mi < 4; mi++) {
                ldm4(a0[mi], aA + mi * 16 * QROWB + ks * 32);
                ldm4(a1[mi], aA + mi * 16 * QROWB + ks * 32 + 128);
            }
            #pragma unroll
            for (int ng = 0; ng < 2; ng++) {
                ldm4(b0[ng], aB + ng * 16 * QROWB + ks * 32);
                ldm4(b1[ng], aB + ng * 16 * QROWB + ks * 32 + 128);
            }
            #pragma unroll
            for (int mi = 0; mi < 4; mi++)
                #pragma unroll
                for (int ng = 0; ng < 2; ng++) {
                    mmas8(accP[mi][2 * ng],     a0[mi], b0[ng][0], b0[ng][2]);
                    mmas8(accP[mi][2 * ng + 1], a0[mi], b0[ng][1], b0[ng][3]);
                    mmas8(accX[mi][2 * ng],     a0[mi], b1[ng][0], b1[ng][2]);
                    mmas8(accX[mi][2 * ng + 1], a0[mi], b1[ng][1], b1[ng][3]);
                    mmas8(accX[mi][2 * ng],     a1[mi], b0[ng][0], b0[ng][2]);
                    mmas8(accX[mi][2 * ng + 1], a1[mi], b0[ng][1], b0[ng][3]);
                }
        }
    }

    const float c256 = 1.f / 256.f;
    int r0base = bm + wm * 64 + (lane >> 2);
    int c0base = bn + wn * 32 + (lane & 3) * 2;
    #pragma unroll
    for (int mi = 0; mi < 4; mi++) {
        int rA = r0base + mi * 16, rB = rA + 8;
        float saA = sav[rA], saB = sav[rB];
        #pragma unroll
        for (int nj = 0; nj < 4; nj++) {
            int col = c0base + nj * 8;
            if (col >= Nreal) continue;   // col even, Nreal even -> pair safe
            float s0 = sbv[col], s1 = sbv[col + 1];
            float bv0 = bias[col], bv1 = bias[col + 1];
            float v0 = fmaxf(saA * s0 * ((float)accP[mi][nj][0] + (float)accX[mi][nj][0] * c256) + bv0, 0.f);
            float v1 = fmaxf(saA * s1 * ((float)accP[mi][nj][1] + (float)accX[mi][nj][1] * c256) + bv1, 0.f);
            float v2 = fmaxf(saB * s0 * ((float)accP[mi][nj][2] + (float)accX[mi][nj][2] * c256) + bv0, 0.f);
            float v3 = fmaxf(saB * s1 * ((float)accP[mi][nj][3] + (float)accX[mi][nj][3] * c256) + bv1, 0.f);
            *(float2*)(C + (size_t)rA * Nreal + col) = make_float2(v0, v1);
            *(float2*)(C + (size_t)rB * Nreal + col) = make_float2(v2, v3);
        }
    }
}

// ===================== bf16 GEMM2 (R6 kernel, EPI=0 path only) ============
#define ROWB 144
#define A_STG (128 * ROWB)
#define B_STG (128 * ROWB)
#define STG   (A_STG + B_STG)
#define GEMM_SMEM (3 * STG)

__global__ __launch_bounds__(128, 2) void k_mma(
    const __nv_bfloat16* __restrict__ A, const __nv_bfloat16* __restrict__ B,
    const float* __restrict__ bias, float* __restrict__ C,
    int Kt, int steps, int Nreal)
{
    extern __shared__ char smem[];
    uint32_t sb = smem_u32(smem);
    int tid = threadIdx.x;
    int lane = tid & 31, wid = tid >> 5;
    int wm = wid & 1, wn = wid >> 1;
    int bm = blockIdx.y * 128, bn = blockIdx.x * 128;

    const char* Abase = (const char*)A + (size_t)bm * Kt * 2;
    const char* Bbase = (const char*)B + (size_t)bn * Kt * 2;
    size_t gsA = (size_t)Kt * 2;

    auto load_stage = [&](int s, int slot) {
        size_t kb = (size_t)s * 128;
        uint32_t base = sb + slot * STG;
        #pragma unroll
        for (int i = 0; i < 8; i++) {
            int c = tid + i * 128;
            int row = c >> 3, kc = c & 7;
            uint32_t dst = base + row * ROWB + kc * 16;
            const char* src = Abase + (size_t)row * gsA + kb + kc * 16;
            asm volatile("cp.async.cg.shared.global [%0], [%1], 16;"
                         :: "r"(dst), "l"(src));
        }
        #pragma unroll
        for (int i = 0; i < 8; i++) {
            int c = tid + i * 128;
            int row = c >> 3, kc = c & 7;
            uint32_t dst = base + A_STG + row * ROWB + kc * 16;
            const char* src = Bbase + (size_t)row * gsA + kb + kc * 16;
            asm volatile("cp.async.cg.shared.global [%0], [%1], 16;"
                         :: "r"(dst), "l"(src));
        }
    };

    float acc[4][8][4];
    #pragma unroll
    for (int i = 0; i < 4; i++)
        #pragma unroll
        for (int j = 0; j < 8; j++)
            #pragma unroll
            for (int q = 0; q < 4; q++) acc[i][j][q] = 0.f;

    load_stage(0, 0);
    asm volatile("cp.async.commit_group;" ::: "memory");
    load_stage(1, 1);
    asm volatile("cp.async.commit_group;" ::: "memory");

    int lr = lane & 15;
    int lc = (lane >> 4) * 16;

    for (int j = 0; j < steps; j++) {
        asm volatile("cp.async.wait_group 1;" ::: "memory");
        __syncthreads();

        if (j + 2 < steps) load_stage(j + 2, (j + 2) % 3);
        asm volatile("cp.async.commit_group;" ::: "memory");

        uint32_t sA = sb + (j % 3) * STG;
        uint32_t sB = sA + A_STG;
        uint32_t aA = sA + (wm * 64 + lr) * ROWB + lc;
        uint32_t aB = sB + (wn * 64 + lr) * ROWB + lc;

        #pragma unroll
        for (int ks = 0; ks < 4; ks++) {
            uint32_t a[4][4], b[4][4];
            #pragma unroll
            for (int mi = 0; mi < 4; mi++)
                ldm4(a[mi], aA + mi * 16 * ROWB + ks * 32);
            #pragma unroll
            for (int ng = 0; ng < 4; ng++)
                ldm4(b[ng], aB + ng * 16 * ROWB + ks * 32);
            #pragma unroll
            for (int mi = 0; mi < 4; mi++)
                #pragma unroll
                for (int ng = 0; ng < 4; ng++) {
                    mma16816(acc[mi][2 * ng],     a[mi], b[ng][0], b[ng][2]);
                    mma16816(acc[mi][2 * ng + 1], a[mi], b[ng][1], b[ng][3]);
                }
        }
    }

    int r0base = bm + wm * 64 + (lane >> 2);
    int c0base = bn + wn * 64 + (lane & 3) * 2;
    #pragma unroll
    for (int mi = 0; mi < 4; mi++) {
        #pragma unroll
        for (int ni = 0; ni < 8; ni++) {
            int col = c0base + ni * 8;
            float bv0 = __ldg(&bias[col]);
            float bv1 = __ldg(&bias[col + 1]);
            int r0 = r0base + mi * 16;
            int r1 = r0 + 8;
            float v0 = fmaxf(acc[mi][ni][0] + bv0, 0.f);
            float v1 = fmaxf(acc[mi][ni][1] + bv1, 0.f);
            float v2 = fmaxf(acc[mi][ni][2] + bv0, 0.f);
            float v3 = fmaxf(acc[mi][ni][3] + bv1, 0.f);
            *(float2*)(C + (size_t)r0 * Nreal + col) = make_float2(v0, v1);
            *(float2*)(C + (size_t)r1 * Nreal + col) = make_float2(v2, v3);
        }
    }
}

// ===================== final skinny layer: warp per row =====================
__global__ __launch_bounds__(256) void k_lin3(
    const float* __restrict__ H, const float* __restrict__ W,
    const float* __restrict__ b, float* __restrict__ out)
{
    __shared__ float Wt[9][1024];
    __shared__ float sb9[9];
    int t = threadIdx.x;
    for (int i = t; i < 9 * 1024; i += 256) {
        int c = i / 1024, k = i - c * 1024;
        Wt[c][k] = W[k * 9 + c];
    }
    if (t < 9) sb9[t] = b[t];
    __syncthreads();

    int w = t >> 5, l = t & 31;
    int row = blockIdx.x * 8 + w;
    const float* h = H + (size_t)row * 1024;

    float acc[9];
    #pragma unroll
    for (int c = 0; c < 9; c++) acc[c] = 0.f;
    #pragma unroll 4
    for (int i = 0; i < 32; i++) {
        int k = l + 32 * i;
        float hv = h[k];
        #pragma unroll
        for (int c = 0; c < 9; c++) acc[c] += hv * Wt[c][k];
    }
    #pragma unroll
    for (int o = 16; o; o >>= 1)
        #pragma unroll
        for (int c = 0; c < 9; c++)
            acc[c] += __shfl_xor_sync(0xFFFFFFFFu, acc[c], o);
    if (l == 0) {
        #pragma unroll
        for (int c = 0; c < 9; c++) out[row * 9 + c] = acc[c] + sb9[c];
    }
}

// ===================== launch =====================
extern "C" void kernel_launch(void* const* d_in, const int* in_sizes, int n_in,
                              void* d_out, int out_size)
{
    const float* x   = (const float*)d_in[0];
    const void*  ei  = d_in[1];
    const float* W1  = (const float*)d_in[3];
    const float* a1s = (const float*)d_in[4];
    const float* a1d = (const float*)d_in[5];
    const float* b1  = (const float*)d_in[6];
    const float* W2  = (const float*)d_in[7];
    const float* a2s = (const float*)d_in[8];
    const float* a2d = (const float*)d_in[9];
    const float* b2  = (const float*)d_in[10];
    const float* W3  = (const float*)d_in[11];
    const float* a3s = (const float*)d_in[12];
    const float* a3d = (const float*)d_in[13];
    const float* b3  = (const float*)d_in[14];
    const float* lW1 = (const float*)d_in[15];
    const float* lb1 = (const float*)d_in[16];
    const float* lW2 = (const float*)d_in[17];
    const float* lb2 = (const float*)d_in[18];
    const float* lW3 = (const float*)d_in[19];
    const float* lb3 = (const float*)d_in[20];

    int N   = in_sizes[0];
    int B   = N / NPG;
    int E   = in_sizes[1] / 2;
    int EPG = E / B;

    float *F, *G, *H, *sa1, *sb1;
    int8_t *A1q, *B1q;
    __nv_bfloat16 *A2, *B2;
    cudaGetSymbolAddress((void**)&F, g_F);
    cudaGetSymbolAddress((void**)&G, g_G);
    cudaGetSymbolAddress((void**)&H, g_H);
    cudaGetSymbolAddress((void**)&A1q, g_A1q);
    cudaGetSymbolAddress((void**)&B1q, g_B1q);
    cudaGetSymbolAddress((void**)&sa1, g_sa1);
    cudaGetSymbolAddress((void**)&sb1, g_sb1);
    cudaGetSymbolAddress((void**)&A2, g_A2);
    cudaGetSymbolAddress((void**)&B2, g_B2);

    cudaFuncSetAttribute(k_mmai8,
        cudaFuncAttributeMaxDynamicSharedMemorySize, QSMEM);
    cudaFuncSetAttribute(k_mma,
        cudaFuncAttributeMaxDynamicSharedMemorySize, GEMM_SMEM);

    k_sniff<<<1, 32>>>((const int*)ei);
    k_res0<<<B, 64>>>(x, F);

    k_gat<1, 8><<<B, 256>>>(x, NPG, ei, E, EPG, W1, a1s, a1d, b1,
                            F, OFF_RES1, OFF_OUT1);
    k_gat<8, 64><<<B, 256>>>(F + OFF_RES1, FDIM, ei, E, EPG, W2, a2s, a2d, b2,
                             F, OFF_RES2, OFF_OUT2);
    k_gat<64, 9><<<B, 256>>>(F + OFF_RES2, FDIM, ei, E, EPG, W3, a3s, a3d, b3,
                             F, OFF_RES3, OFF_OUT3);

    // weight prep
    k_quantB<<<5000, 256>>>(lW1, B1q, sb1, 3280, 5000, K1Q);
    {
        dim3 blk(32, 8);
        dim3 g2((1024 + 31) / 32, (5000 + 31) / 32);
        k_splitB<<<g2, blk>>>(lW2, B2, 5000, 1024, K2P);
    }

    // A1 quant from F
    k_quantA<<<BGR, 256>>>(F, A1q, sa1, FDIM, K1Q);

    // GEMM1 (int8) -> G fp32
    {
        dim3 grid(N1PAD / 128, BGR / 128);   // 40 x 32
        k_mmai8<<<grid, 256, QSMEM>>>(A1q, B1q, sa1, sb1, lb1, G,
                                      K1Q, K1Q / 128, 5000);
    }

    // A2 split (bf16 3-term) from G
    k_splitA<<<BGR, 256>>>(G, A2, 5000, K2P);

    // GEMM2 (bf16) -> H
    {
        dim3 grid(1024 / 128, BGR / 128);    // 8 x 32
        k_mma<<<grid, 128, GEMM_SMEM>>>(A2, B2, lb2, H, K2T, K2T / 64, 1024);
    }

    k_lin3<<<BGR / 8, 256>>>(H, lW3, lb3, (float*)d_out);
}

// round 13
// speedup vs baseline: 1.8755x; 1.8755x over previous
#include <cuda_runtime.h>
#include <cuda_bf16.h>
#include <stdint.h>

#define NPG  39
#define FDIM 3280
#define BGR  4096
#define MAXE (NPG * 9)

// Frow offsets (concat order)
#define OFF_RES1 39
#define OFF_RES2 351
#define OFF_RES3 2847
#define OFF_OUT0 3198
#define OFF_OUT1 3199
#define OFF_OUT2 3207
#define OFF_OUT3 3271

// GEMM1: K=3280, K' = 3*3280=9840 -> pad to 9856 (154 * 64)
// GEMM2: K=5000, K' = 15000 -> pad to 15040 (235 * 64)
#define K1SEC 3280
#define K1TT  9856
#define K2SEC 5000
#define K2TT  15040
#define N1PAD 5120

__device__ float g_H[(size_t)BGR * 1024];
__device__ __align__(128) __nv_bfloat16 g_A1[(size_t)BGR * K1TT];
__device__ __align__(128) __nv_bfloat16 g_B1[(size_t)N1PAD * K1TT];
__device__ __align__(128) __nv_bfloat16 g_A2[(size_t)BGR * K2TT];
__device__ __align__(128) __nv_bfloat16 g_B2[(size_t)1024 * K2TT];
__device__ int g_is64;

__device__ __forceinline__ uint32_t smem_u32(const void* p) {
    uint32_t a;
    asm("{ .reg .u64 t; cvta.to.shared.u64 t, %1; cvt.u32.u64 %0, t; }"
        : "=r"(a) : "l"(p));
    return a;
}

__global__ void k_sniff(const int* __restrict__ ei) {
    if (threadIdx.x == 0) g_is64 = (ei[8] == 0) ? 1 : 0;
}

// ===================== fused GAT layer (device) =====================
template <int FIN, int FOUT>
__device__ __forceinline__ void gat_layer(
    int t,
    const float* __restrict__ xin,            // smem [39*FIN]
    const float* __restrict__ W, const float* __restrict__ as_,
    const float* __restrict__ ad_, const float* __restrict__ bias,
    float* __restrict__ out, float* __restrict__ maxout,  // smem Frow regions
    float* __restrict__ sh, float* __restrict__ sW,
    float* __restrict__ sas, float* __restrict__ sad, float* __restrict__ sb,
    float* __restrict__ ss, float* __restrict__ sd, float* __restrict__ sden,
    float* __restrict__ sew, const short* __restrict__ sse,
    const int* __restrict__ cnt)
{
    for (int i = t; i < FIN * FOUT; i += 256) sW[i] = W[i];
    if (t < FOUT) { sas[t] = as_[t]; sad[t] = ad_[t]; sb[t] = bias[t]; }
    __syncthreads();

    // h = xin @ W
    if (FOUT % 4 == 0) {
        constexpr int F4 = FOUT / 4;
        for (int idx = t; idx < NPG * F4; idx += 256) {
            int i = idx / F4, f4 = idx - i * F4;
            float4 a = make_float4(0.f, 0.f, 0.f, 0.f);
            #pragma unroll
            for (int k = 0; k < FIN; k++) {
                float xv = xin[i * FIN + k];
                float4 wv = *(const float4*)&sW[k * FOUT + f4 * 4];
                a.x += xv * wv.x; a.y += xv * wv.y;
                a.z += xv * wv.z; a.w += xv * wv.w;
            }
            *(float4*)&sh[i * FOUT + f4 * 4] = a;
        }
    } else {
        for (int idx = t; idx < NPG * FOUT; idx += 256) {
            int i = idx / FOUT, f = idx - i * FOUT;
            float a = 0.f;
            #pragma unroll 8
            for (int k = 0; k < FIN; k++) a += xin[i * FIN + k] * sW[k * FOUT + f];
            sh[idx] = a;
        }
    }
    __syncthreads();

    // attention projections
    for (int i = t; i < NPG; i += 256) {
        float a = 0.f, b = 0.f;
        #pragma unroll
        for (int f = 0; f < FOUT; f++) {
            a += sh[i * FOUT + f] * sas[f];
            b += sh[i * FOUT + f] * sad[f];
        }
        ss[i] = a; sd[i] = b;
    }
    __syncthreads();

    // segment softmax in sorted domain (no atomics)
    for (int i = t; i < NPG; i += 256) {
        int e0 = cnt[i], e1 = cnt[i + 1];
        float di = sd[i];
        float mx = -1e30f;
        for (int p = e0; p < e1; p++) {
            float sc = ss[sse[p]] + di;
            sc = sc > 0.f ? sc : 0.2f * sc;
            sew[p] = sc;
            mx = fmaxf(mx, sc);
        }
        float s = 0.f;
        for (int p = e0; p < e1; p++) {
            float w = __expf(sew[p] - mx);
            sew[p] = w;
            s += w;
        }
        sden[i] = s;
    }
    __syncthreads();

    // aggregation
    if (FOUT % 4 == 0) {
        constexpr int F4 = FOUT / 4;
        for (int idx = t; idx < NPG * F4; idx += 256) {
            int i = idx / F4, f4 = idx - i * F4;
            float4 a = make_float4(0.f, 0.f, 0.f, 0.f);
            int e0 = cnt[i], e1 = cnt[i + 1];
            for (int p = e0; p < e1; p++) {
                float w = sew[p];
                float4 hv = *(const float4*)&sh[(int)sse[p] * FOUT + f4 * 4];
                a.x += w * hv.x; a.y += w * hv.y;
                a.z += w * hv.z; a.w += w * hv.w;
            }
            float inv = 1.f / (sden[i] + 1e-16f);
            int base = i * FOUT + f4 * 4;
            out[base + 0] = fmaxf(a.x * inv + sb[f4 * 4 + 0], 0.f);
            out[base + 1] = fmaxf(a.y * inv + sb[f4 * 4 + 1], 0.f);
            out[base + 2] = fmaxf(a.z * inv + sb[f4 * 4 + 2], 0.f);
            out[base + 3] = fmaxf(a.w * inv + sb[f4 * 4 + 3], 0.f);
        }
    } else {
        for (int idx = t; idx < NPG * FOUT; idx += 256) {
            int i = idx / FOUT, f = idx - i * FOUT;
            float a = 0.f;
            int e0 = cnt[i], e1 = cnt[i + 1];
            for (int p = e0; p < e1; p++)
                a += sew[p] * sh[(int)sse[p] * FOUT + f];
            out[idx] = fmaxf(a / (sden[i] + 1e-16f) + sb[f], 0.f);
        }
    }
    __syncthreads();

    // per-feature max over nodes
    for (int f = t; f < FOUT; f += 256) {
        float mv = out[f];
        for (int i = 1; i < NPG; i++) mv = fmaxf(mv, out[i * FOUT + f]);
        maxout[f] = mv;
    }
    __syncthreads();
}

// ===================== fused GAT kernel =====================
// One CTA per graph: x -> 3 GAT layers -> full 3280 feature row in smem
// -> split-bf16 A1 row [hi|hi|lo] (K1TT stride) directly.
__global__ __launch_bounds__(256) void k_fgat(
    const float* __restrict__ x, const void* __restrict__ edges,
    int E, int EPG,
    const float* __restrict__ W1, const float* __restrict__ a1s,
    const float* __restrict__ a1d, const float* __restrict__ b1,
    const float* __restrict__ W2, const float* __restrict__ a2s,
    const float* __restrict__ a2d, const float* __restrict__ b2,
    const float* __restrict__ W3, const float* __restrict__ a3s,
    const float* __restrict__ a3d, const float* __restrict__ b3,
    __nv_bfloat16* __restrict__ A1)
{
    __shared__ __align__(16) float Frow[FDIM];
    __shared__ __align__(16) float sh[NPG * 64];
    __shared__ __align__(16) float sW[64 * 9];
    __shared__ float sas[64], sad[64], sb[64];
    __shared__ float ss[NPG], sd[NPG], sden[NPG];
    __shared__ float sew[MAXE];
    __shared__ short elsA[MAXE], eldA[MAXE], sse[MAXE];
    __shared__ int cnt[NPG + 1], off[NPG];

    int g = blockIdx.x;
    int t = threadIdx.x;
    int nE = EPG + NPG;

    if (t < NPG) Frow[t] = x[g * NPG + t];
    if (t < NPG + 1) cnt[t] = 0;
    __syncthreads();

    // decode edges + histogram (once for all layers)
    bool is64 = (g_is64 != 0);
    long long node0 = (long long)g * NPG;
    for (int e = t; e < nE; e += 256) {
        int ls, ld;
        if (e < EPG) {
            long long ge = (long long)g * EPG + e;
            long long sv, dv;
            if (is64) {
                const long long* p = (const long long*)edges;
                sv = p[ge]; dv = p[ge + E];
            } else {
                const int* p = (const int*)edges;
                sv = p[ge]; dv = p[ge + E];
            }
            ls = (int)(sv - node0);
            ld = (int)(dv - node0);
        } else {
            ls = ld = e - EPG;   // self loop
        }
        elsA[e] = (short)ls; eldA[e] = (short)ld;
        atomicAdd(&cnt[ld], 1);
    }
    __syncthreads();

    if (t == 0) {
        int s = 0;
        for (int i = 0; i < NPG; i++) {
            int c = cnt[i];
            cnt[i] = s; off[i] = s;
            s += c;
        }
        cnt[NPG] = s;
    }
    __syncthreads();

    for (int e = t; e < nE; e += 256) {
        int pos = atomicAdd(&off[eldA[e]], 1);
        sse[pos] = elsA[e];
    }
    // out0 = max over x
    if (t == 32) {          // warp 1, avoids waiting on warp 0 scatter
        float mv = Frow[0];
        for (int i = 1; i < NPG; i++) mv = fmaxf(mv, Frow[i]);
        Frow[OFF_OUT0] = mv;
    }
    __syncthreads();

    gat_layer<1, 8>(t, &Frow[0], W1, a1s, a1d, b1,
                    &Frow[OFF_RES1], &Frow[OFF_OUT1],
                    sh, sW, sas, sad, sb, ss, sd, sden, sew, sse, cnt);
    gat_layer<8, 64>(t, &Frow[OFF_RES1], W2, a2s, a2d, b2,
                     &Frow[OFF_RES2], &Frow[OFF_OUT2],
                     sh, sW, sas, sad, sb, ss, sd, sden, sew, sse, cnt);
    gat_layer<64, 9>(t, &Frow[OFF_RES2], W3, a3s, a3d, b3,
                     &Frow[OFF_RES3], &Frow[OFF_OUT3],
                     sh, sW, sas, sad, sb, ss, sd, sden, sew, sse, cnt);

    // epilogue: split-bf16 A1 row [hi | hi | lo]
    __nv_bfloat16* row = A1 + (size_t)g * K1TT;
    for (int k = t; k < FDIM; k += 256) {
        float v = Frow[k];
        __nv_bfloat16 hi = __float2bfloat16(v);
        __nv_bfloat16 lo = __float2bfloat16(v - __bfloat162float(hi));
        row[k] = hi;
        row[K1SEC + k] = hi;
        row[2 * K1SEC + k] = lo;
    }
}

// ===================== weight split (B: [hi | lo | hi], stride KtT) ========
__global__ void k_splitB(const float* __restrict__ W, __nv_bfloat16* __restrict__ Bt,
                         int K, int N, int KtT)
{
    __shared__ float tile[32][33];
    int kb = blockIdx.y * 32, nb = blockIdx.x * 32;
    int tx = threadIdx.x, ty = threadIdx.y;
    for (int r = ty; r < 32; r += 8) {
        int k = kb + r, n = nb + tx;
        tile[r][tx] = (k < K && n < N) ? W[(size_t)k * N + n] : 0.f;
    }
    __syncthreads();
    for (int r = ty; r < 32; r += 8) {
        int n = nb + r, k = kb + tx;
        if (n < N && k < K) {
            float v = tile[tx][r];
            __nv_bfloat16 hi = __float2bfloat16(v);
            __nv_bfloat16 lo = __float2bfloat16(v - __bfloat162float(hi));
            __nv_bfloat16* row = Bt + (size_t)n * KtT;
            row[k] = hi;
            row[K + k] = lo;
            row[2 * K + k] = hi;
        }
    }
}

// ===================== mma.sync GEMM (R8 machinery) =====================
#define ROWB 144
#define A_STG (128 * ROWB)
#define B_STG (128 * ROWB)
#define STG   (A_STG + B_STG)
#define GEMM_SMEM (3 * STG)

__device__ __forceinline__ void ldm4(uint32_t* r, uint32_t addr) {
    asm volatile("ldmatrix.sync.aligned.m8n8.x4.shared.b16 {%0,%1,%2,%3}, [%4];"
        : "=r"(r[0]), "=r"(r[1]), "=r"(r[2]), "=r"(r[3]) : "r"(addr));
}
__device__ __forceinline__ void mma16816(float* c, const uint32_t* a,
                                         uint32_t b0, uint32_t b1) {
    asm volatile("mma.sync.aligned.m16n8k16.row.col.f32.bf16.bf16.f32 "
        "{%0,%1,%2,%3}, {%4,%5,%6,%7}, {%8,%9}, {%0,%1,%2,%3};"
        : "+f"(c[0]), "+f"(c[1]), "+f"(c[2]), "+f"(c[3])
        : "r"(a[0]), "r"(a[1]), "r"(a[2]), "r"(a[3]), "r"(b0), "r"(b1));
}

// split-write two adjacent cols into [hi|hi|lo] row (section KSec, stride KsT)
__device__ __forceinline__ void wsplit2(__nv_bfloat16* base, int r, int KsT,
                                        int KSec, int col, float v0, float v1) {
    __nv_bfloat16 h0 = __float2bfloat16(v0);
    __nv_bfloat16 h1 = __float2bfloat16(v1);
    __nv_bfloat162 lo2 = __floats2bfloat162_rn(v0 - __bfloat162float(h0),
                                               v1 - __bfloat162float(h1));
    uint32_t hp; { __nv_bfloat162 hh; hh.x = h0; hh.y = h1; hp = *(uint32_t*)&hh; }
    uint32_t lp = *(uint32_t*)&lo2;
    __nv_bfloat16* row = base + (size_t)r * KsT;
    *(uint32_t*)(row + col) = hp;
    *(uint32_t*)(row + KSec + col) = hp;
    *(uint32_t*)(row + 2 * KSec + col) = lp;
}

template <int EPI>
__global__ __launch_bounds__(128, 2) void k_mma(
    const __nv_bfloat16* __restrict__ A, const __nv_bfloat16* __restrict__ B,
    const float* __restrict__ bias, float* __restrict__ C,
    __nv_bfloat16* __restrict__ Csp, int KsT, int KSec,
    int Kt, int steps, int Nreal)
{
    extern __shared__ char smem[];
    uint32_t sb = smem_u32(smem);
    int tid = threadIdx.x;
    int lane = tid & 31, wid = tid >> 5;
    int wm = wid & 1, wn = wid >> 1;
    int bm = blockIdx.y * 128, bn = blockIdx.x * 128;

    const char* Abase = (const char*)A + (size_t)bm * Kt * 2;
    const char* Bbase = (const char*)B + (size_t)bn * Kt * 2;
    size_t gsA = (size_t)Kt * 2;

    auto load_stage = [&](int s, int slot) {
        size_t kb = (size_t)s * 128;
        uint32_t base = sb + slot * STG;
        #pragma unroll
        for (int i = 0; i < 8; i++) {
            int c = tid + i * 128;
            int row = c >> 3, kc = c & 7;
            uint32_t dst = base + row * ROWB + kc * 16;
            const char* src = Abase + (size_t)row * gsA + kb + kc * 16;
            asm volatile("cp.async.cg.shared.global [%0], [%1], 16;"
                         :: "r"(dst), "l"(src));
        }
        #pragma unroll
        for (int i = 0; i < 8; i++) {
            int c = tid + i * 128;
            int row = c >> 3, kc = c & 7;
            uint32_t dst = base + A_STG + row * ROWB + kc * 16;
            const char* src = Bbase + (size_t)row * gsA + kb + kc * 16;
            asm volatile("cp.async.cg.shared.global [%0], [%1], 16;"
                         :: "r"(dst), "l"(src));
        }
    };

    float acc[4][8][4];
    #pragma unroll
    for (int i = 0; i < 4; i++)
        #pragma unroll
        for (int j = 0; j < 8; j++)
            #pragma unroll
            for (int q = 0; q < 4; q++) acc[i][j][q] = 0.f;

    load_stage(0, 0);
    asm volatile("cp.async.commit_group;" ::: "memory");
    load_stage(1, 1);
    asm volatile("cp.async.commit_group;" ::: "memory");

    int lr = lane & 15;
    int lc = (lane >> 4) * 16;

    for (int j = 0; j < steps; j++) {
        asm volatile("cp.async.wait_group 1;" ::: "memory");
        __syncthreads();

        if (j + 2 < steps) load_stage(j + 2, (j + 2) % 3);
        asm volatile("cp.async.commit_group;" ::: "memory");

        uint32_t sA = sb + (j % 3) * STG;
        uint32_t sB = sA + A_STG;
        uint32_t aA = sA + (wm * 64 + lr) * ROWB + lc;
        uint32_t aB = sB + (wn * 64 + lr) * ROWB + lc;

        #pragma unroll
        for (int ks = 0; ks < 4; ks++) {
            uint32_t a[4][4], b[4][4];
            #pragma unroll
            for (int mi = 0; mi < 4; mi++)
                ldm4(a[mi], aA + mi * 16 * ROWB + ks * 32);
            #pragma unroll
            for (int ng = 0; ng < 4; ng++)
                ldm4(b[ng], aB + ng * 16 * ROWB + ks * 32);
            #pragma unroll
            for (int mi = 0; mi < 4; mi++)
                #pragma unroll
                for (int ng = 0; ng < 4; ng++) {
                    mma16816(acc[mi][2 * ng],     a[mi], b[ng][0], b[ng][2]);
                    mma16816(acc[mi][2 * ng + 1], a[mi], b[ng][1], b[ng][3]);
                }
        }
    }

    int r0base = bm + wm * 64 + (lane >> 2);
    int c0base = bn + wn * 64 + (lane & 3) * 2;
    #pragma unroll
    for (int mi = 0; mi < 4; mi++) {
        #pragma unroll
        for (int ni = 0; ni < 8; ni++) {
            int col = c0base + ni * 8;
            if (EPI == 1 && col >= Nreal) continue;  // col even, Nreal even
            float bv0 = __ldg(&bias[col]);
            float bv1 = __ldg(&bias[col + 1]);
            int r0 = r0base + mi * 16;
            int r1 = r0 + 8;
            float v0 = fmaxf(acc[mi][ni][0] + bv0, 0.f);
            float v1 = fmaxf(acc[mi][ni][1] + bv1, 0.f);
            float v2 = fmaxf(acc[mi][ni][2] + bv0, 0.f);
            float v3 = fmaxf(acc[mi][ni][3] + bv1, 0.f);
            if (EPI == 0) {
                *(float2*)(C + (size_t)r0 * Nreal + col) = make_float2(v0, v1);
                *(float2*)(C + (size_t)r1 * Nreal + col) = make_float2(v2, v3);
            } else {
                wsplit2(Csp, r0, KsT, KSec, col, v0, v1);
                wsplit2(Csp, r1, KsT, KSec, col, v2, v3);
            }
        }
    }
}

// ===================== final skinny layer: warp per row =====================
__global__ __launch_bounds__(256) void k_lin3(
    const float* __restrict__ H, const float* __restrict__ W,
    const float* __restrict__ b, float* __restrict__ out)
{
    __shared__ float Wt[9][1024];
    __shared__ float sb9[9];
    int t = threadIdx.x;
    for (int i = t; i < 9 * 1024; i += 256) {
        int c = i / 1024, k = i - c * 1024;
        Wt[c][k] = W[k * 9 + c];
    }
    if (t < 9) sb9[t] = b[t];
    __syncthreads();

    int w = t >> 5, l = t & 31;
    int row = blockIdx.x * 8 + w;
    const float* h = H + (size_t)row * 1024;

    float acc[9];
    #pragma unroll
    for (int c = 0; c < 9; c++) acc[c] = 0.f;
    #pragma unroll 4
    for (int i = 0; i < 32; i++) {
        int k = l + 32 * i;
        float hv = h[k];
        #pragma unroll
        for (int c = 0; c < 9; c++) acc[c] += hv * Wt[c][k];
    }
    #pragma unroll
    for (int o = 16; o; o >>= 1)
        #pragma unroll
        for (int c = 0; c < 9; c++)
            acc[c] += __shfl_xor_sync(0xFFFFFFFFu, acc[c], o);
    if (l == 0) {
        #pragma unroll
        for (int c = 0; c < 9; c++) out[row * 9 + c] = acc[c] + sb9[c];
    }
}

// ===================== launch =====================
extern "C" void kernel_launch(void* const* d_in, const int* in_sizes, int n_in,
                              void* d_out, int out_size)
{
    const float* x   = (const float*)d_in[0];
    const void*  ei  = d_in[1];
    const float* W1  = (const float*)d_in[3];
    const float* a1s = (const float*)d_in[4];
    const float* a1d = (const float*)d_in[5];
    const float* b1  = (const float*)d_in[6];
    const float* W2  = (const float*)d_in[7];
    const float* a2s = (const float*)d_in[8];
    const float* a2d = (const float*)d_in[9];
    const float* b2  = (const float*)d_in[10];
    const float* W3  = (const float*)d_in[11];
    const float* a3s = (const float*)d_in[12];
    const float* a3d = (const float*)d_in[13];
    const float* b3  = (const float*)d_in[14];
    const float* lW1 = (const float*)d_in[15];
    const float* lb1 = (const float*)d_in[16];
    const float* lW2 = (const float*)d_in[17];
    const float* lb2 = (const float*)d_in[18];
    const float* lW3 = (const float*)d_in[19];
    const float* lb3 = (const float*)d_in[20];

    int N   = in_sizes[0];
    int B   = N / NPG;
    int E   = in_sizes[1] / 2;
    int EPG = E / B;

    float *H;
    __nv_bfloat16 *A1, *B1, *A2, *B2;
    cudaGetSymbolAddress((void**)&H, g_H);
    cudaGetSymbolAddress((void**)&A1, g_A1);
    cudaGetSymbolAddress((void**)&B1, g_B1);
    cudaGetSymbolAddress((void**)&A2, g_A2);
    cudaGetSymbolAddress((void**)&B2, g_B2);

    cudaFuncSetAttribute(k_mma<0>,
        cudaFuncAttributeMaxDynamicSharedMemorySize, GEMM_SMEM);
    cudaFuncSetAttribute(k_mma<1>,
        cudaFuncAttributeMaxDynamicSharedMemorySize, GEMM_SMEM);

    k_sniff<<<1, 32>>>((const int*)ei);

    // weight prep
    {
        dim3 blk(32, 8);
        dim3 g1((5000 + 31) / 32, (3280 + 31) / 32);
        k_splitB<<<g1, blk>>>(lW1, B1, 3280, 5000, K1TT);
        dim3 g2((1024 + 31) / 32, (5000 + 31) / 32);
        k_splitB<<<g2, blk>>>(lW2, B2, 5000, 1024, K2TT);
    }

    // fused: res0 + 3 GAT layers + split-bf16 A1 row
    k_fgat<<<B, 256>>>(x, ei, E, EPG,
                       W1, a1s, a1d, b1, W2, a2s, a2d, b2, W3, a3s, a3d, b3,
                       A1);

    // GEMM1 -> A2 (split bf16, sections of K2SEC, stride K2TT)
    {
        dim3 grid(N1PAD / 128, BGR / 128);   // 40 x 32
        k_mma<1><<<grid, 128, GEMM_SMEM>>>(A1, B1, lb1, (float*)nullptr,
                                           A2, K2TT, K2SEC,
                                           K1TT, K1TT / 64, 5000);
    }

    // GEMM2 -> H
    {
        dim3 grid(1024 / 128, BGR / 128);    // 8 x 32
        k_mma<0><<<grid, 128, GEMM_SMEM>>>(A2, B2, lb2, H,
                                           (__nv_bfloat16*)nullptr, 0, 0,
                                           K2TT, K2TT / 64, 1024);
    }

    k_lin3<<<BGR / 8, 256>>>(H, lW3, lb3, (float*)d_out);
}